// round 5
// baseline (speedup 1.0000x reference)
#include <cuda_runtime.h>
#include <math.h>

#define DIM 4096

// First 30 primes (== P_DIAG == P_OFF for DIM=4096).
__constant__ int c_primes[30] = {
    2, 3, 5, 7, 11, 13, 17, 19, 23, 29,
    31, 37, 41, 43, 47, 53, 59, 61, 67, 71,
    73, 79, 83, 89, 97, 101, 103, 107, 109, 113};

// Established layout (R1-R4 fault forensics): output is the REAL PART of H,
// DIM*DIM float32 elements (64 MiB). Inputs are 3 float32 scalars.
//
// Math reduction: off-diagonal prime terms are purely imaginary, so
// Re(H) is diagonal: Re(H)[n,n] = Re(exp(-s*ln n)) + theta*ln(p)*corr*zeta2/p
// (at primes) + reg, where reg = max(1e-22, ||diag||_F * 1e-18) and the
// Frobenius norm sees only the (real) diagonal since the imaginary
// off-diagonals cancel exactly under 0.5*(H + H^dagger).
//
// One block, 1024 threads, 4 entries/thread: fp64 internal math, block
// norm reduction, fused float32 scatter onto the pre-zeroed output.
__global__ __launch_bounds__(1024, 1)
void diag_kernel(const float* sr_p, const float* si_p, const float* th_p,
                 float* __restrict__ out) {
    const double ZETA2 = 1.6449340668482264365;  // pi^2/6
    const double CUTOFF = 1e-80;

    const double sr = sr_p ? (double)*sr_p : 0.5;
    const double si = si_p ? (double)*si_p : 14.134725141734693;
    const double th = th_p ? (double)*th_p : 1e-22;

    const bool in_range = (fabs(sr) < 30.0) && (fabs(si) < 500.0);
    const double corr = fmin(sqrt(sr * sr + si * si), 5.0);

    double local[4];
    double ss = 0.0;

#pragma unroll
    for (int k = 0; k < 4; k++) {
        const int n = threadIdx.x + k * 1024 + 1;  // 1..4096
        const double logn = log((double)n);
        const bool safe = (-sr * logn) > -80.0;
        // Re(exp(-s*ln n)) = exp(-sr*ln n) * cos(si*ln n)
        double re = (in_range || safe) ? exp(-sr * logn) * cos(si * logn)
                                       : CUTOFF;
        if (n <= 113) {
            bool isp = false;
#pragma unroll
            for (int j = 0; j < 30; j++) isp = isp || (n == c_primes[j]);
            if (isp) re += th * logn * corr * (ZETA2 / (double)n);
        }
        local[k] = re;
        ss += re * re;
    }

    // Block reduction: sum of squares -> Frobenius norm -> reg
    __shared__ double warp_s[32];
    __shared__ double s_reg;
#pragma unroll
    for (int o = 16; o > 0; o >>= 1)
        ss += __shfl_down_sync(0xffffffffu, ss, o);
    const int lane = threadIdx.x & 31;
    const int wid = threadIdx.x >> 5;
    if (lane == 0) warp_s[wid] = ss;
    __syncthreads();
    if (wid == 0) {
        double v = warp_s[lane];
#pragma unroll
        for (int o = 16; o > 0; o >>= 1)
            v += __shfl_down_sync(0xffffffffu, v, o);
        if (lane == 0) s_reg = fmax(1e-22, sqrt(v) * 1e-18);
    }
    __syncthreads();
    const double reg = s_reg;

    // Scatter diagonal as float32. Last byte written:
    // (4095*4097)*4 + 4 = 67,108,864 = out_size*4 exactly (in bounds).
#pragma unroll
    for (int k = 0; k < 4; k++) {
        const size_t i = threadIdx.x + k * 1024;  // 0..4095
        out[i * (size_t)(DIM + 1)] = (float)(local[k] + reg);
    }
}

extern "C" void kernel_launch(void* const* d_in, const int* in_sizes, int n_in,
                              void* d_out, int out_size) {
    (void)in_sizes;
    const float* sr = (n_in >= 1) ? (const float*)d_in[0] : 0;
    const float* si = (n_in >= 2) ? (const float*)d_in[1] : 0;
    const float* th = (n_in >= 3) ? (const float*)d_in[2] : 0;

    // float32 output: zero exactly out_size elements * 4 bytes = 64 MiB.
    // This is the minimum element size of any plausible dtype, so the
    // memset can never exceed the allocation.
    cudaMemsetAsync(d_out, 0, (size_t)out_size * 4u, 0);

    diag_kernel<<<1, 1024>>>(sr, si, th, (float*)d_out);
}

// round 6
// speedup vs baseline: 4.9711x; 4.9711x over previous
#include <cuda_runtime.h>
#include <math.h>

#define DIM 4096
#define NBLK 32          // diag-compute blocks
#define TPB  128         // threads per diag block (NBLK*TPB == DIM)

// First 30 primes (== P_DIAG == P_OFF for DIM=4096).
__constant__ int c_primes[30] = {
    2, 3, 5, 7, 11, 13, 17, 19, 23, 29,
    31, 37, 41, 43, 47, 53, 59, 61, 67, 71,
    73, 79, 83, 89, 97, 101, 103, 107, 109, 113};

// Scratch (static __device__ globals: allocation-free).
__device__ double g_diag[DIM];
__device__ double g_partial[NBLK];
__device__ double g_reg;
__device__ unsigned int g_count;   // zero-initialized; self-resets each call

// ---------------------------------------------------------------------------
// Kernel A: compute diag in fp64 across 32 SMs (1 element/thread), reduce
// sum-of-squares to block partials; the LAST block to finish folds the
// partials into g_reg = max(1e-22, ||diag|| * 1e-18) and resets the counter
// (deterministic across graph replays).
// ---------------------------------------------------------------------------
__global__ __launch_bounds__(TPB, 1)
void diag_compute_kernel(const float* sr_p, const float* si_p,
                         const float* th_p) {
    const double ZETA2 = 1.6449340668482264365;  // pi^2/6
    const double CUTOFF = 1e-80;

    const double sr = sr_p ? (double)*sr_p : 0.5;
    const double si = si_p ? (double)*si_p : 14.134725141734693;
    const double th = th_p ? (double)*th_p : 1e-22;

    const bool in_range = (fabs(sr) < 30.0) && (fabs(si) < 500.0);
    const double corr = fmin(sqrt(sr * sr + si * si), 5.0);

    const int t = blockIdx.x * TPB + threadIdx.x;   // 0..4095
    const int n = t + 1;                            // 1..4096

    const double logn = log((double)n);
    const bool safe = (-sr * logn) > -80.0;
    // Re(exp(-s*ln n)) = exp(-sr*ln n) * cos(si*ln n)
    double re = (in_range || safe) ? exp(-sr * logn) * cos(si * logn)
                                   : CUTOFF;
    if (n <= 113) {
        bool isp = false;
#pragma unroll
        for (int j = 0; j < 30; j++) isp = isp || (n == c_primes[j]);
        if (isp) re += th * logn * corr * (ZETA2 / (double)n);
    }
    g_diag[t] = re;

    // Block reduction of re^2 (128 threads = 4 warps).
    double ss = re * re;
#pragma unroll
    for (int o = 16; o > 0; o >>= 1)
        ss += __shfl_down_sync(0xffffffffu, ss, o);
    __shared__ double warp_s[4];
    const int lane = threadIdx.x & 31;
    const int wid = threadIdx.x >> 5;
    if (lane == 0) warp_s[wid] = ss;
    __syncthreads();

    __shared__ bool is_last;
    if (threadIdx.x == 0) {
        g_partial[blockIdx.x] = warp_s[0] + warp_s[1] + warp_s[2] + warp_s[3];
        __threadfence();
        unsigned int old = atomicAdd(&g_count, 1u);
        is_last = (old == NBLK - 1);
    }
    __syncthreads();
    if (is_last && threadIdx.x == 0) {
        double s = 0.0;
#pragma unroll
        for (int i = 0; i < NBLK; i++)
            s += ((volatile double*)g_partial)[i];
        g_reg = fmax(1e-22, sqrt(s) * 1e-18);
        __threadfence();
        g_count = 0;  // reset for next graph replay
    }
}

// ---------------------------------------------------------------------------
// Kernel B: fused zero-fill + diagonal splice. One float4 (16 B) per thread,
// 4,194,304 threads covering the 64 MiB output exactly. A thread's float4
// contains a diagonal element iff col4 == row>>2 (1/1024 threads).
// ---------------------------------------------------------------------------
__global__ __launch_bounds__(256, 8)
void fill_kernel(float4* __restrict__ out) {
    const unsigned int idx = blockIdx.x * 256u + threadIdx.x;  // 0..4194303
    const unsigned int row = idx >> 10;        // 1024 float4 per row
    const unsigned int col4 = idx & 1023u;

    float4 v = make_float4(0.f, 0.f, 0.f, 0.f);
    if (col4 == (row >> 2)) {
        const float d = (float)(g_diag[row] + g_reg);
        switch (row & 3u) {
            case 0: v.x = d; break;
            case 1: v.y = d; break;
            case 2: v.z = d; break;
            default: v.w = d; break;
        }
    }
    out[idx] = v;
}

extern "C" void kernel_launch(void* const* d_in, const int* in_sizes, int n_in,
                              void* d_out, int out_size) {
    (void)in_sizes; (void)out_size;
    const float* sr = (n_in >= 1) ? (const float*)d_in[0] : 0;
    const float* si = (n_in >= 2) ? (const float*)d_in[1] : 0;
    const float* th = (n_in >= 3) ? (const float*)d_in[2] : 0;

    diag_compute_kernel<<<NBLK, TPB>>>(sr, si, th);
    // 4096*4096 floats / 4 per thread-store = 4,194,304 threads = 16384 blocks
    fill_kernel<<<16384, 256>>>((float4*)d_out);
}